// round 10
// baseline (speedup 1.0000x reference)
#include <cuda_runtime.h>

// SNN MLP restructured:
//   k1: static_input = inp @ W1^T (fp32 SGEMM 16384x800x784, LDS-balanced 8x8 tile)
//       + fused 32-step LIF -> uint8 spike counts (device scratch, 13 MB)
//   k2: out = (counts @ W2^T) / 32
// Both kernels split into 2 launches so ncu (-s 5 -c 1) profiles k1's 2nd half.

#define BM 256
#define BN 64
#define BK 16
#define TM 8
#define TN 8
#define PADA 4
#define PADB 4
#define KDIM 784
#define NDIM 800
#define MDIM 16384
#define MHALF (MDIM / 2)
#define KTILES (KDIM / BK)   // 49

// Spike counts 0..32 fit in uint8 exactly.
__device__ unsigned char g_s[(size_t)MDIM * NDIM];

__global__ __launch_bounds__(256, 2)
void snn_fc1_lif_kernel(const float* __restrict__ A,   // [16384, 784]
                        const float* __restrict__ W1,  // [800, 784]
                        int m_base)
{
    __shared__ float As[2][BK][BM + PADA];
    __shared__ float Bs[2][BK][BN + PADB];

    const int tid = threadIdx.x;
    const int tx  = tid & 7;    // 0..7  (N dir, TN=8)
    const int ty  = tid >> 3;   // 0..31 (M dir, TM=8)
    const int m0  = m_base + blockIdx.y * BM;
    const int n0  = blockIdx.x * BN;

    // Global loads: A tile 256x16 = 1024 float4 (4/thread), B tile 64x16 = 256 float4 (1/thread)
    const int arow = tid >> 2;          // 0..63, +{0,64,128,192}
    const int ak4  = tid & 3;
    const int brow = tid >> 2;
    const int bk4  = tid & 3;

    const float* Ar0 = A + (size_t)(m0 + arow)       * KDIM + ak4 * 4;
    const float* Ar1 = A + (size_t)(m0 + arow + 64)  * KDIM + ak4 * 4;
    const float* Ar2 = A + (size_t)(m0 + arow + 128) * KDIM + ak4 * 4;
    const float* Ar3 = A + (size_t)(m0 + arow + 192) * KDIM + ak4 * 4;
    const bool  bvalid = (n0 + brow) < NDIM;
    const float* Br = W1 + (size_t)(n0 + brow) * KDIM + bk4 * 4;

    float4 a0, a1, a2, a3, b0;
    a0 = *(const float4*)(Ar0);
    a1 = *(const float4*)(Ar1);
    a2 = *(const float4*)(Ar2);
    a3 = *(const float4*)(Ar3);
    b0 = bvalid ? *(const float4*)(Br) : make_float4(0.f, 0.f, 0.f, 0.f);

#define STORE_TILE(B_)                                                     \
    do {                                                                   \
        As[B_][ak4 * 4 + 0][arow]       = a0.x;                            \
        As[B_][ak4 * 4 + 1][arow]       = a0.y;                            \
        As[B_][ak4 * 4 + 2][arow]       = a0.z;                            \
        As[B_][ak4 * 4 + 3][arow]       = a0.w;                            \
        As[B_][ak4 * 4 + 0][arow + 64]  = a1.x;                            \
        As[B_][ak4 * 4 + 1][arow + 64]  = a1.y;                            \
        As[B_][ak4 * 4 + 2][arow + 64]  = a1.z;                            \
        As[B_][ak4 * 4 + 3][arow + 64]  = a1.w;                            \
        As[B_][ak4 * 4 + 0][arow + 128] = a2.x;                            \
        As[B_][ak4 * 4 + 1][arow + 128] = a2.y;                            \
        As[B_][ak4 * 4 + 2][arow + 128] = a2.z;                            \
        As[B_][ak4 * 4 + 3][arow + 128] = a2.w;                            \
        As[B_][ak4 * 4 + 0][arow + 192] = a3.x;                            \
        As[B_][ak4 * 4 + 1][arow + 192] = a3.y;                            \
        As[B_][ak4 * 4 + 2][arow + 192] = a3.z;                            \
        As[B_][ak4 * 4 + 3][arow + 192] = a3.w;                            \
        Bs[B_][bk4 * 4 + 0][brow]       = b0.x;                            \
        Bs[B_][bk4 * 4 + 1][brow]       = b0.y;                            \
        Bs[B_][bk4 * 4 + 2][brow]       = b0.z;                            \
        Bs[B_][bk4 * 4 + 3][brow]       = b0.w;                            \
    } while (0)

    STORE_TILE(0);
    __syncthreads();

    float acc[TM][TN];
#pragma unroll
    for (int i = 0; i < TM; i++)
#pragma unroll
        for (int j = 0; j < TN; j++) acc[i][j] = 0.f;

    int buf = 0;
    for (int t = 0; t < KTILES; ++t) {
        if (t + 1 < KTILES) {
            const int ko = (t + 1) * BK;
            a0 = *(const float4*)(Ar0 + ko);
            a1 = *(const float4*)(Ar1 + ko);
            a2 = *(const float4*)(Ar2 + ko);
            a3 = *(const float4*)(Ar3 + ko);
            b0 = bvalid ? *(const float4*)(Br + ko)
                        : make_float4(0.f, 0.f, 0.f, 0.f);
        }
#pragma unroll
        for (int kk = 0; kk < BK; ++kk) {
            float4 ra0 = *(const float4*)&As[buf][kk][ty * TM];
            float4 ra1 = *(const float4*)&As[buf][kk][ty * TM + 4];
            float4 rb0 = *(const float4*)&Bs[buf][kk][tx * TN];
            float4 rb1 = *(const float4*)&Bs[buf][kk][tx * TN + 4];
            float am[TM] = {ra0.x, ra0.y, ra0.z, ra0.w, ra1.x, ra1.y, ra1.z, ra1.w};
            float bn[TN] = {rb0.x, rb0.y, rb0.z, rb0.w, rb1.x, rb1.y, rb1.z, rb1.w};
#pragma unroll
            for (int i = 0; i < TM; i++)
#pragma unroll
                for (int j = 0; j < TN; j++)
                    acc[i][j] = fmaf(am[i], bn[j], acc[i][j]);
        }
        if (t + 1 < KTILES) {
            STORE_TILE(buf ^ 1);
            __syncthreads();
            buf ^= 1;
        }
    }
#undef STORE_TILE

    // ---- Fused LIF: mem = 0.95*mem + 0.05*c; spike iff mem > 1; mem -= 1 on spike.
    // __f*_rn intrinsics: no FMA contraction; matches reference ordering.
    const int nb = n0 + tx * TN;
    if (nb < NDIM) {
#pragma unroll
        for (int i = 0; i < TM; i++) {
            float mem[TN];
            unsigned int cnt[TN];
#pragma unroll
            for (int j = 0; j < TN; j++) { mem[j] = 0.f; cnt[j] = 0u; }
            for (int s = 0; s < 32; ++s) {
#pragma unroll
                for (int j = 0; j < TN; j++) {
                    mem[j] = __fadd_rn(__fmul_rn(0.95f, mem[j]),
                                       __fmul_rn(0.05f, acc[i][j]));
                    if (mem[j] > 1.0f) {
                        cnt[j] += 1u;
                        mem[j] -= 1.0f;
                    }
                }
            }
            const int m = m0 + ty * TM + i;
            uint2 packed;
            packed.x = cnt[0] | (cnt[1] << 8) | (cnt[2] << 16) | (cnt[3] << 24);
            packed.y = cnt[4] | (cnt[5] << 8) | (cnt[6] << 16) | (cnt[7] << 24);
            *(uint2*)&g_s[(size_t)m * NDIM + nb] = packed;
        }
    }
}

// out[b,k] = (sum_j counts[b,j] * W2[k,j]) / 32 ; one warp per row.
__global__ __launch_bounds__(256)
void snn_fc2_kernel(const float* __restrict__ W2,   // [10, 800]
                    float* __restrict__ out,        // [16384, 10]
                    int row_base)
{
    __shared__ float W2s[10 * NDIM];   // direct copy: W2s[k*800 + j]
    const int tid = threadIdx.x;
    for (int i = tid; i < 10 * NDIM; i += 256) W2s[i] = W2[i];
    __syncthreads();

    const int warp = tid >> 5;
    const int lane = tid & 31;
    const int row  = row_base + blockIdx.x * 8 + warp;

    float acc[10];
#pragma unroll
    for (int k = 0; k < 10; k++) acc[k] = 0.f;

    const unsigned char* __restrict__ srow = g_s + (size_t)row * NDIM;
#pragma unroll 5
    for (int it = 0; it < 25; ++it) {
        const int j = it * 32 + lane;               // consecutive lanes -> consecutive j
        const float sv = (float)srow[j];
#pragma unroll
        for (int k = 0; k < 10; k++)
            acc[k] = fmaf(sv, W2s[k * NDIM + j], acc[k]);  // conflict-free LDS
    }
#pragma unroll
    for (int k = 0; k < 10; k++) {
#pragma unroll
        for (int off = 16; off; off >>= 1)
            acc[k] += __shfl_xor_sync(0xffffffffu, acc[k], off);
    }
    if (lane < 10)
        out[row * 10 + lane] = acc[lane] * 0.03125f;   // exact /32
}

extern "C" void kernel_launch(void* const* d_in, const int* in_sizes, int n_in,
                              void* d_out, int out_size)
{
    const float* inp = (const float*)d_in[0];   // [16384,1,28,28] -> [16384,784]
    const float* W1  = (const float*)d_in[1];   // [800,784]
    const float* W2  = (const float*)d_in[2];   // [10,800]
    float* out = (float*)d_out;                 // [16384,10]

    dim3 grid1((NDIM + BN - 1) / BN, MHALF / BM);   // (13, 32) per half
    // 4-launch pattern: ncu -s 5 profiles index 5 = second fc1 launch.
    snn_fc1_lif_kernel<<<grid1, 256>>>(inp, W1, 0);
    snn_fc1_lif_kernel<<<grid1, 256>>>(inp, W1, MHALF);
    snn_fc2_kernel<<<MHALF / 8, 256>>>(W2, out, 0);
    snn_fc2_kernel<<<MHALF / 8, 256>>>(W2, out, MHALF);
}